// round 2
// baseline (speedup 1.0000x reference)
#include <cuda_runtime.h>
#include <math.h>

// Fixed problem shapes: B*T = 8192 tokens, H = 2048, S = 32, r = 16, ad = 32, topk = 2
#define HDIM 2048
#define SDIM 32
#define RDIM 16
#define ADIM 32
#define TTOT 8192
#define NASS (2 * TTOT)   // total assignments = 16384

// ---- static device scratch (no allocations allowed) ----
__device__ int   d_cnt[SDIM];
__device__ int   d_off[SDIM];
__device__ int4  d_pair[TTOT];                  // per token: {s1, pos1, s2, pos2}
__device__ int   d_btok[SDIM * TTOT];           // bucket -> token id
__device__ float d_bc[SDIM * TTOT];             // bucket -> combined coefficient g*alpha
__device__ __align__(16) float d_hU[2][SDIM * TTOT * RDIM];   // K-split partial h@U
__device__ __align__(16) float d_part[(size_t)NASS * HDIM];   // per-assignment output rows

// ---------------------------------------------------------------------------
// Kernel 0: reset bucket counters
// ---------------------------------------------------------------------------
__global__ void reset_kernel() {
    if (threadIdx.x < SDIM) d_cnt[threadIdx.x] = 0;
}

// ---------------------------------------------------------------------------
// Kernel 1: router. Tiled GEMM sc = h @ Wr^T (64 tok x 32 s per block), then a
// strictly per-thread serial top-2 + softmax + renorm + attribute gate, and
// bucket scatter. No warp collectives anywhere.
// ---------------------------------------------------------------------------
__global__ void __launch_bounds__(256) router_kernel(
    const float* __restrict__ h, const float* __restrict__ Wr,
    const float* __restrict__ attr, const float* __restrict__ Wa) {
    __shared__ float sh[64][33];
    __shared__ float sw[32][33];
    __shared__ float ssc[64][33];
    __shared__ float saw[SDIM];

    int tid = threadIdx.x;
    int t0  = blockIdx.x * 64;

    if (tid < SDIM) {
        float a = 0.f;
#pragma unroll
        for (int j = 0; j < ADIM; j++) a += attr[tid * ADIM + j] * Wa[j];
        saw[tid] = 1.0f / (1.0f + expf(-a));
    }

    int tg = tid & 31, sg = tid >> 5;   // tokens {tg, tg+32}, schemas {4sg..4sg+3}
    float acc0[4] = {0.f, 0.f, 0.f, 0.f};
    float acc1[4] = {0.f, 0.f, 0.f, 0.f};

    for (int k0 = 0; k0 < HDIM; k0 += 32) {
        __syncthreads();
        for (int idx = tid; idx < 64 * 32; idx += 256)
            sh[idx >> 5][idx & 31] = h[(size_t)(t0 + (idx >> 5)) * HDIM + k0 + (idx & 31)];
        for (int idx = tid; idx < 32 * 32; idx += 256)
            sw[idx >> 5][idx & 31] = Wr[(size_t)(idx >> 5) * HDIM + k0 + (idx & 31)];
        __syncthreads();
#pragma unroll
        for (int k = 0; k < 32; k++) {
            float a0 = sh[tg][k], a1 = sh[tg + 32][k];
#pragma unroll
            for (int j = 0; j < 4; j++) {
                float b = sw[4 * sg + j][k];
                acc0[j] += a0 * b;
                acc1[j] += a1 * b;
            }
        }
    }
    __syncthreads();
#pragma unroll
    for (int j = 0; j < 4; j++) {
        ssc[tg][4 * sg + j]      = acc0[j];
        ssc[tg + 32][4 * sg + j] = acc1[j];
    }
    __syncthreads();

    // One thread per token: serial top-2 + softmax + scatter.
    if (tid < 64) {
        int t = t0 + tid;
        float m = ssc[tid][0];
        int   i1 = 0;
#pragma unroll
        for (int s2 = 1; s2 < SDIM; s2++) {
            float v = ssc[tid][s2];
            if (v > m) { m = v; i1 = s2; }
        }
        float m2 = -3.4e38f;
        int   i2 = (i1 == 0) ? 1 : 0;
#pragma unroll
        for (int s2 = 0; s2 < SDIM; s2++) {
            if (s2 == i1) continue;
            float v = ssc[tid][s2];
            if (v > m2) { m2 = v; i2 = s2; }
        }
        float Z = 0.f;
#pragma unroll
        for (int s2 = 0; s2 < SDIM; s2++) Z += expf(ssc[tid][s2] - m);
        float g0 = 1.0f / Z;             // exp(m-m)/Z
        float g1 = expf(m2 - m) / Z;
        float gs = g0 + g1 + 1e-8f;      // matches reference renorm epsilon
        g0 /= gs; g1 /= gs;
        float alpha = 0.9f + 0.2f * (g0 * saw[i1] + g1 * saw[i2]);

        int p1 = atomicAdd(&d_cnt[i1], 1);
        int p2 = atomicAdd(&d_cnt[i2], 1);
        if (p1 >= TTOT) p1 = TTOT - 1;   // impossible by construction; hard guard
        if (p2 >= TTOT) p2 = TTOT - 1;
        d_btok[i1 * TTOT + p1] = t;
        d_bc  [i1 * TTOT + p1] = g0 * alpha;
        d_btok[i2 * TTOT + p2] = t;
        d_bc  [i2 * TTOT + p2] = g1 * alpha;
        d_pair[t] = make_int4(i1, p1, i2, p2);
    }
}

// ---------------------------------------------------------------------------
// Kernel 2: exclusive scan of bucket counts (serial, 1 thread; 32 values)
// ---------------------------------------------------------------------------
__global__ void scan_kernel() {
    if (threadIdx.x == 0 && blockIdx.x == 0) {
        int acc = 0;
        for (int s = 0; s < SDIM; s++) { d_off[s] = acc; acc += d_cnt[s]; }
    }
}

// ---------------------------------------------------------------------------
// Kernel 3: grouped hU = h_rows @ U[s]. Per block: 128 assignments x 16 r,
// K half selected by blockIdx.z (partials into d_hU[z]).
// ---------------------------------------------------------------------------
__global__ void __launch_bounds__(256) hu_kernel(
    const float* __restrict__ h, const float* __restrict__ U) {
    int s = blockIdx.y;
    int base = blockIdx.x * 128;
    int kz = blockIdx.z;
    int n = d_cnt[s] - base;
    if (n <= 0) return;
    if (n > 128) n = 128;

    __shared__ float sh[128][65];
    __shared__ __align__(16) float su[64][16];
    __shared__ int stok[128];

    int tid = threadIdx.x;
    if (tid < 128) {
        int slot = (tid < n) ? tid : 0;              // padding rows re-read a valid token
        stok[tid] = d_btok[s * TTOT + base + slot];
    }
    __syncthreads();

    int tg = tid & 63, rg = tid >> 6;                // tokens {tg, tg+64}, r {4rg..4rg+3}
    float acc0[4] = {0.f, 0.f, 0.f, 0.f};
    float acc1[4] = {0.f, 0.f, 0.f, 0.f};
    int k0base = kz * (HDIM / 2);

    for (int kc = 0; kc < HDIM / 2; kc += 64) {
        int k0 = k0base + kc;
        __syncthreads();
        for (int idx = tid; idx < 128 * 64; idx += 256) {
            int row = idx >> 6, col = idx & 63;
            sh[row][col] = h[(size_t)stok[row] * HDIM + k0 + col];
        }
        for (int idx = tid; idx < 64 * 16; idx += 256)
            su[idx >> 4][idx & 15] =
                U[(size_t)s * HDIM * RDIM + (size_t)(k0 + (idx >> 4)) * RDIM + (idx & 15)];
        __syncthreads();
#pragma unroll 8
        for (int k = 0; k < 64; k++) {
            float a0 = sh[tg][k], a1 = sh[tg + 64][k];
            float4 b = *(const float4*)&su[k][4 * rg];
            acc0[0] += a0 * b.x; acc0[1] += a0 * b.y; acc0[2] += a0 * b.z; acc0[3] += a0 * b.w;
            acc1[0] += a1 * b.x; acc1[1] += a1 * b.y; acc1[2] += a1 * b.z; acc1[3] += a1 * b.w;
        }
    }

    float* hu = d_hU[kz];
    if (tg < n)
        *(float4*)&hu[(size_t)(s * TTOT + base + tg) * RDIM + 4 * rg] =
            make_float4(acc0[0], acc0[1], acc0[2], acc0[3]);
    if (tg + 64 < n)
        *(float4*)&hu[(size_t)(s * TTOT + base + tg + 64) * RDIM + 4 * rg] =
            make_float4(acc1[0], acc1[1], acc1[2], acc1[3]);
}

// ---------------------------------------------------------------------------
// Kernel 4: grouped partial rows: d_part[gid] = (c * hU_row) @ V[s] for a
// 512-wide H slice. Pure STG stores to contiguous compact rows — no atomics.
// ---------------------------------------------------------------------------
__global__ void __launch_bounds__(256) outA_kernel(const float* __restrict__ V) {
    int s = blockIdx.y;
    int base = blockIdx.x * 128;
    int hq = blockIdx.z;
    int n = d_cnt[s] - base;
    if (n <= 0) return;
    if (n > 128) n = 128;
    int gbase = d_off[s] + base;

    __shared__ float shu[128][17];
    __shared__ __align__(16) float sv[16][128];

    int tid = threadIdx.x;
    for (int idx = tid; idx < 128 * 16; idx += 256) {
        int slot = idx >> 4, r = idx & 15;
        float v = 0.f;
        if (slot < n) {
            size_t a = (size_t)(s * TTOT + base + slot);
            v = d_bc[a] * (d_hU[0][a * RDIM + r] + d_hU[1][a * RDIM + r]);
        }
        shu[slot][r] = v;
    }

    int h0 = hq * 512;
    int hg = tid & 7, tokg = tid >> 3;               // h chunk {16hg..+15}, slots {tokg+32i}

    for (int hc = 0; hc < 512; hc += 128) {
        __syncthreads();
        for (int idx = tid; idx < 16 * 128; idx += 256) {
            int r = idx >> 7, hh = idx & 127;
            sv[r][hh] = V[(size_t)s * RDIM * HDIM + (size_t)r * HDIM + h0 + hc + hh];
        }
        __syncthreads();

        float acc[4][16];
#pragma unroll
        for (int i = 0; i < 4; i++)
#pragma unroll
            for (int j = 0; j < 16; j++) acc[i][j] = 0.f;

#pragma unroll
        for (int r = 0; r < 16; r++) {
            float a0 = shu[tokg][r];
            float a1 = shu[tokg + 32][r];
            float a2 = shu[tokg + 64][r];
            float a3 = shu[tokg + 96][r];
#pragma unroll
            for (int jj = 0; jj < 4; jj++) {
                float4 b = *(const float4*)&sv[r][hg * 16 + 4 * jj];
                acc[0][4 * jj + 0] += a0 * b.x; acc[0][4 * jj + 1] += a0 * b.y;
                acc[0][4 * jj + 2] += a0 * b.z; acc[0][4 * jj + 3] += a0 * b.w;
                acc[1][4 * jj + 0] += a1 * b.x; acc[1][4 * jj + 1] += a1 * b.y;
                acc[1][4 * jj + 2] += a1 * b.z; acc[1][4 * jj + 3] += a1 * b.w;
                acc[2][4 * jj + 0] += a2 * b.x; acc[2][4 * jj + 1] += a2 * b.y;
                acc[2][4 * jj + 2] += a2 * b.z; acc[2][4 * jj + 3] += a2 * b.w;
                acc[3][4 * jj + 0] += a3 * b.x; acc[3][4 * jj + 1] += a3 * b.y;
                acc[3][4 * jj + 2] += a3 * b.z; acc[3][4 * jj + 3] += a3 * b.w;
            }
        }

#pragma unroll
        for (int i = 0; i < 4; i++) {
            int slot = tokg + 32 * i;
            if (slot < n) {
                float* p = &d_part[(size_t)(gbase + slot) * HDIM + h0 + hc + hg * 16];
#pragma unroll
                for (int jj = 0; jj < 4; jj++)
                    *(float4*)(p + 4 * jj) = make_float4(acc[i][4 * jj + 0], acc[i][4 * jj + 1],
                                                         acc[i][4 * jj + 2], acc[i][4 * jj + 3]);
            }
        }
    }
}

// ---------------------------------------------------------------------------
// Kernel 5: per-token gather: out[t] = part[g1] + part[g2]. Fixed add order ->
// bitwise deterministic regardless of bucket fill order.
// ---------------------------------------------------------------------------
__global__ void __launch_bounds__(256) gather_kernel(float* __restrict__ out) {
    int t = blockIdx.x;
    int4 pr = d_pair[t];
    int g1 = d_off[pr.x] + pr.y;
    int g2 = d_off[pr.z] + pr.w;
    if (g1 < 0 || g1 >= NASS) g1 = 0;   // hard guards; unreachable by construction
    if (g2 < 0 || g2 >= NASS) g2 = 0;
    const float4* p1 = (const float4*)&d_part[(size_t)g1 * HDIM];
    const float4* p2 = (const float4*)&d_part[(size_t)g2 * HDIM];
    float4* po = (float4*)&out[(size_t)t * HDIM];
#pragma unroll
    for (int i = threadIdx.x; i < HDIM / 4; i += 256) {
        float4 a = p1[i], b = p2[i];
        po[i] = make_float4(a.x + b.x, a.y + b.y, a.z + b.z, a.w + b.w);
    }
}

// ---------------------------------------------------------------------------
// Launch
// ---------------------------------------------------------------------------
extern "C" void kernel_launch(void* const* d_in, const int* in_sizes, int n_in,
                              void* d_out, int out_size) {
    const float* h    = (const float*)d_in[0];
    const float* Wr   = (const float*)d_in[1];
    const float* U    = (const float*)d_in[2];
    const float* V    = (const float*)d_in[3];
    const float* attr = (const float*)d_in[4];
    const float* Wa   = (const float*)d_in[5];
    float* out = (float*)d_out;

    reset_kernel<<<1, 32>>>();
    router_kernel<<<TTOT / 64, 256>>>(h, Wr, attr, Wa);
    scan_kernel<<<1, 32>>>();
    hu_kernel<<<dim3(TTOT / 128, SDIM, 2), 256>>>(h, U);
    outA_kernel<<<dim3(TTOT / 128, SDIM, 4), 256>>>(V);
    gather_kernel<<<TTOT, 256>>>(out);
}

// round 5
// speedup vs baseline: 2.3180x; 2.3180x over previous
#include <cuda_runtime.h>
#include <math.h>

// Fixed shapes: B*T = 8192 tokens, H = 2048, S = 32, r = 16, ad = 32, topk = 2
#define HDIM 2048
#define SDIM 32
#define RDIM 16
#define ADIM 32
#define TTOT 8192
#define NASS (2 * TTOT)

// ---- static device scratch ----
__device__ int   d_cnt[SDIM];
__device__ int   d_off[SDIM];
__device__ int4  d_pair[TTOT];
__device__ int   d_btok[SDIM * TTOT];
__device__ float d_bc[SDIM * TTOT];
__device__ __align__(16) float d_hU[2][SDIM * TTOT * RDIM];
__device__ __align__(16) float d_part[(size_t)NASS * HDIM];

// ---- cp.async helpers ----
__device__ __forceinline__ void cp16(void* dst_smem, const void* src) {
    unsigned d = (unsigned)__cvta_generic_to_shared(dst_smem);
    asm volatile("cp.async.cg.shared.global [%0], [%1], 16;" :: "r"(d), "l"(src));
}
__device__ __forceinline__ void cp_commit() { asm volatile("cp.async.commit_group;"); }
template <int N> __device__ __forceinline__ void cp_wait() {
    asm volatile("cp.async.wait_group %0;" :: "n"(N));
}

// ---------------------------------------------------------------------------
// Kernel 0: reset bucket counters
// ---------------------------------------------------------------------------
__global__ void reset_kernel() {
    if (threadIdx.x < SDIM) d_cnt[threadIdx.x] = 0;
}

// ---------------------------------------------------------------------------
// Kernel 1: router GEMM (64 tok x 32 s per block, K tiles of 32, cp.async
// double buffered) + per-thread serial top-2/softmax/gate + bucket scatter.
// ---------------------------------------------------------------------------
__global__ void __launch_bounds__(256) router_kernel(
    const float* __restrict__ h, const float* __restrict__ Wr,
    const float* __restrict__ attr, const float* __restrict__ Wa) {
    // rows stored with stride 9 float4-chunks (8 data + 1 pad) -> conflict-free LDS.128
    __shared__ float4 sh[2][64 * 9];
    __shared__ float4 sw[2][32 * 9];
    __shared__ float  ssc[64][33];
    __shared__ float  saw[SDIM];

    int tid = threadIdx.x;
    int t0  = blockIdx.x * 64;

    if (tid < SDIM) {
        float a = 0.f;
#pragma unroll
        for (int j = 0; j < ADIM; j++) a += attr[tid * ADIM + j] * Wa[j];
        saw[tid] = 1.0f / (1.0f + expf(-a));
    }

    int tg = tid & 31, sg = tid >> 5;   // tokens {tg, tg+32}; schemas {4sg..4sg+3}
    float acc0[4] = {0.f, 0.f, 0.f, 0.f};
    float acc1[4] = {0.f, 0.f, 0.f, 0.f};

    const int NT = HDIM / 32;           // 64 K-tiles

    auto load_tile = [&](int kt, int b) {
        int k0 = kt * 32;
#pragma unroll
        for (int i = tid; i < 512; i += 256) {   // 64 rows x 8 chunks
            int row = i >> 3, c = i & 7;
            cp16(&sh[b][row * 9 + c], h + (size_t)(t0 + row) * HDIM + k0 + c * 4);
        }
        {                                        // 32 rows x 8 chunks
            int row = tid >> 3, c = tid & 7;
            cp16(&sw[b][row * 9 + c], Wr + (size_t)row * HDIM + k0 + c * 4);
        }
        cp_commit();
    };

    load_tile(0, 0);
    for (int kt = 0; kt < NT; kt++) {
        int b = kt & 1;
        if (kt + 1 < NT) { load_tile(kt + 1, b ^ 1); cp_wait<1>(); }
        else             { cp_wait<0>(); }
        __syncthreads();
        const float4* H4 = sh[b];
        const float4* W4 = sw[b];
#pragma unroll
        for (int c = 0; c < 8; c++) {
            float4 a0 = H4[tg * 9 + c];
            float4 a1 = H4[(tg + 32) * 9 + c];
#pragma unroll
            for (int j = 0; j < 4; j++) {
                float4 w = W4[(4 * sg + j) * 9 + c];
                acc0[j] += a0.x * w.x; acc0[j] += a0.y * w.y;
                acc0[j] += a0.z * w.z; acc0[j] += a0.w * w.w;
                acc1[j] += a1.x * w.x; acc1[j] += a1.y * w.y;
                acc1[j] += a1.z * w.z; acc1[j] += a1.w * w.w;
            }
        }
        __syncthreads();
    }

#pragma unroll
    for (int j = 0; j < 4; j++) {
        ssc[tg][4 * sg + j]      = acc0[j];
        ssc[tg + 32][4 * sg + j] = acc1[j];
    }
    __syncthreads();

    if (tid < 64) {     // strictly per-thread serial top-2 + softmax
        int t = t0 + tid;
        float m = ssc[tid][0];
        int   i1 = 0;
#pragma unroll
        for (int s2 = 1; s2 < SDIM; s2++) {
            float v = ssc[tid][s2];
            if (v > m) { m = v; i1 = s2; }
        }
        float m2 = -3.4e38f;
        int   i2 = (i1 == 0) ? 1 : 0;
#pragma unroll
        for (int s2 = 0; s2 < SDIM; s2++) {
            if (s2 == i1) continue;
            float v = ssc[tid][s2];
            if (v > m2) { m2 = v; i2 = s2; }
        }
        float Z = 0.f;
#pragma unroll
        for (int s2 = 0; s2 < SDIM; s2++) Z += expf(ssc[tid][s2] - m);
        float g0 = 1.0f / Z;
        float g1 = expf(m2 - m) / Z;
        float gs = g0 + g1 + 1e-8f;
        g0 /= gs; g1 /= gs;
        float alpha = 0.9f + 0.2f * (g0 * saw[i1] + g1 * saw[i2]);

        int p1 = atomicAdd(&d_cnt[i1], 1);
        int p2 = atomicAdd(&d_cnt[i2], 1);
        if (p1 >= TTOT) p1 = TTOT - 1;
        if (p2 >= TTOT) p2 = TTOT - 1;
        d_btok[i1 * TTOT + p1] = t;
        d_bc  [i1 * TTOT + p1] = g0 * alpha;
        d_btok[i2 * TTOT + p2] = t;
        d_bc  [i2 * TTOT + p2] = g1 * alpha;
        d_pair[t] = make_int4(i1, p1, i2, p2);
    }
}

// ---------------------------------------------------------------------------
// Kernel 2: serial exclusive scan of 32 bucket counts
// ---------------------------------------------------------------------------
__global__ void scan_kernel() {
    if (threadIdx.x == 0 && blockIdx.x == 0) {
        int acc = 0;
        for (int s = 0; s < SDIM; s++) { d_off[s] = acc; acc += d_cnt[s]; }
    }
}

// ---------------------------------------------------------------------------
// Kernel 3: grouped hU = h_rows @ U[s]. 128 assignments x 16 r per block,
// K half via blockIdx.z, K tiles of 32, cp.async double buffered.
// ---------------------------------------------------------------------------
__global__ void __launch_bounds__(256) hu_kernel(
    const float* __restrict__ h, const float* __restrict__ U) {
    int s = blockIdx.y;
    int base = blockIdx.x * 128;
    int kz = blockIdx.z;
    int n = d_cnt[s] - base;
    if (n <= 0) return;
    if (n > 128) n = 128;

    __shared__ float4 sh[2][128 * 9];      // 128 rows x (8 data + 1 pad) chunks
    __shared__ float4 su[2][32 * 4];       // 32 k-rows x 16 floats
    __shared__ int stok[128];

    int tid = threadIdx.x;
    if (tid < 128) {
        int slot = (tid < n) ? tid : 0;
        stok[tid] = d_btok[s * TTOT + base + slot];
    }
    __syncthreads();

    int tg = tid & 63, rg = tid >> 6;      // tokens {tg, tg+64}; r {4rg..4rg+3}
    float acc0[4] = {0.f, 0.f, 0.f, 0.f};
    float acc1[4] = {0.f, 0.f, 0.f, 0.f};
    int k0base = kz * (HDIM / 2);
    const int NT = (HDIM / 2) / 32;        // 32 K-tiles

    auto load_tile = [&](int kt, int b) {
        int k0 = k0base + kt * 32;
#pragma unroll
        for (int i = tid; i < 1024; i += 256) {   // 128 rows x 8 chunks
            int row = i >> 3, c = i & 7;
            cp16(&sh[b][row * 9 + c], h + (size_t)stok[row] * HDIM + k0 + c * 4);
        }
        if (tid < 128) {                          // 32 k x 4 chunks
            int k = tid >> 2, c = tid & 3;
            cp16(&su[b][k * 4 + c],
                 U + (size_t)s * HDIM * RDIM + (size_t)(k0 + k) * RDIM + c * 4);
        }
        cp_commit();
    };

    load_tile(0, 0);
    for (int kt = 0; kt < NT; kt++) {
        int b = kt & 1;
        if (kt + 1 < NT) { load_tile(kt + 1, b ^ 1); cp_wait<1>(); }
        else             { cp_wait<0>(); }
        __syncthreads();
        const float4* H4 = sh[b];
        const float4* U4 = su[b];
#pragma unroll
        for (int c = 0; c < 8; c++) {
            float4 a0 = H4[tg * 9 + c];
            float4 a1 = H4[(tg + 64) * 9 + c];
            float a0v[4] = {a0.x, a0.y, a0.z, a0.w};
            float a1v[4] = {a1.x, a1.y, a1.z, a1.w};
#pragma unroll
            for (int i = 0; i < 4; i++) {
                float4 bb = U4[(4 * c + i) * 4 + rg];   // warp broadcast
                acc0[0] += a0v[i] * bb.x; acc0[1] += a0v[i] * bb.y;
                acc0[2] += a0v[i] * bb.z; acc0[3] += a0v[i] * bb.w;
                acc1[0] += a1v[i] * bb.x; acc1[1] += a1v[i] * bb.y;
                acc1[2] += a1v[i] * bb.z; acc1[3] += a1v[i] * bb.w;
            }
        }
        __syncthreads();
    }

    float* hu = d_hU[kz];
    if (tg < n)
        *(float4*)&hu[(size_t)(s * TTOT + base + tg) * RDIM + 4 * rg] =
            make_float4(acc0[0], acc0[1], acc0[2], acc0[3]);
    if (tg + 64 < n)
        *(float4*)&hu[(size_t)(s * TTOT + base + tg + 64) * RDIM + 4 * rg] =
            make_float4(acc1[0], acc1[1], acc1[2], acc1[3]);
}

// ---------------------------------------------------------------------------
// Kernel 4: d_part[gid] = (c * hU_row) @ V[s] for a 512-wide H slice.
// V tiles cp.async double buffered. Conflict-free fragment mapping 4hg+32jj.
// ---------------------------------------------------------------------------
__global__ void __launch_bounds__(256) outA_kernel(const float* __restrict__ V) {
    int s = blockIdx.y;
    int base = blockIdx.x * 128;
    int hq = blockIdx.z;
    int n = d_cnt[s] - base;
    if (n <= 0) return;
    if (n > 128) n = 128;
    int gbase = d_off[s] + base;

    __shared__ float  shu[128][17];
    __shared__ float4 sv[2][16 * 32];      // 16 r-rows x 128 floats

    int tid = threadIdx.x;
    for (int idx = tid; idx < 128 * 16; idx += 256) {
        int slot = idx >> 4, r = idx & 15;
        float v = 0.f;
        if (slot < n) {
            size_t a = (size_t)(s * TTOT + base + slot);
            v = d_bc[a] * (d_hU[0][a * RDIM + r] + d_hU[1][a * RDIM + r]);
        }
        shu[slot][r] = v;
    }

    int h0 = hq * 512;
    int hg = tid & 7, tokg = tid >> 3;     // h lanes 4hg+32jj; slots tokg+32i
    const float* Vs = V + (size_t)s * RDIM * HDIM;

    auto load_tile = [&](int ht, int b) {
#pragma unroll
        for (int i = tid; i < 512; i += 256) {    // 16 rows x 32 chunks
            int r = i >> 5, c = i & 31;
            cp16(&sv[b][r * 32 + c], Vs + (size_t)r * HDIM + h0 + ht * 128 + c * 4);
        }
        cp_commit();
    };

    load_tile(0, 0);
    for (int ht = 0; ht < 4; ht++) {
        int b = ht & 1;
        if (ht + 1 < 4) { load_tile(ht + 1, b ^ 1); cp_wait<1>(); }
        else            { cp_wait<0>(); }
        __syncthreads();

        float4 acc[4][4];
#pragma unroll
        for (int i = 0; i < 4; i++)
#pragma unroll
            for (int j = 0; j < 4; j++) acc[i][j] = make_float4(0.f, 0.f, 0.f, 0.f);

        const float4* V4 = sv[b];
#pragma unroll
        for (int r = 0; r < 16; r++) {
            float a0 = shu[tokg][r];
            float a1 = shu[tokg + 32][r];
            float a2 = shu[tokg + 64][r];
            float a3 = shu[tokg + 96][r];
#pragma unroll
            for (int jj = 0; jj < 4; jj++) {
                float4 bb = V4[r * 32 + hg + 8 * jj];   // phase-distinct banks
                acc[0][jj].x += a0 * bb.x; acc[0][jj].y += a0 * bb.y;
                acc[0][jj].z += a0 * bb.z; acc[0][jj].w += a0 * bb.w;
                acc[1][jj].x += a1 * bb.x; acc[1][jj].y += a1 * bb.y;
                acc[1][jj].z += a1 * bb.z; acc[1][jj].w += a1 * bb.w;
                acc[2][jj].x += a2 * bb.x; acc[2][jj].y += a2 * bb.y;
                acc[2][jj].z += a2 * bb.z; acc[2][jj].w += a2 * bb.w;
                acc[3][jj].x += a3 * bb.x; acc[3][jj].y += a3 * bb.y;
                acc[3][jj].z += a3 * bb.z; acc[3][jj].w += a3 * bb.w;
            }
        }

#pragma unroll
        for (int i = 0; i < 4; i++) {
            int slot = tokg + 32 * i;
            if (slot < n) {
                float* p = &d_part[(size_t)(gbase + slot) * HDIM + h0 + ht * 128 + 4 * hg];
#pragma unroll
                for (int jj = 0; jj < 4; jj++)
                    *(float4*)(p + 32 * jj) = acc[i][jj];
            }
        }
        __syncthreads();
    }
}

// ---------------------------------------------------------------------------
// Kernel 5: out[t] = part[g1] + part[g2] (fixed order -> deterministic)
// ---------------------------------------------------------------------------
__global__ void __launch_bounds__(256) gather_kernel(float* __restrict__ out) {
    int t = blockIdx.x;
    int4 pr = d_pair[t];
    int g1 = d_off[pr.x] + pr.y;
    int g2 = d_off[pr.z] + pr.w;
    if (g1 < 0 || g1 >= NASS) g1 = 0;
    if (g2 < 0 || g2 >= NASS) g2 = 0;
    const float4* p1 = (const float4*)&d_part[(size_t)g1 * HDIM];
    const float4* p2 = (const float4*)&d_part[(size_t)g2 * HDIM];
    float4* po = (float4*)&out[(size_t)t * HDIM];
#pragma unroll
    for (int i = threadIdx.x; i < HDIM / 4; i += 256) {
        float4 a = p1[i], b = p2[i];
        po[i] = make_float4(a.x + b.x, a.y + b.y, a.z + b.z, a.w + b.w);
    }
}

// ---------------------------------------------------------------------------
// Launch
// ---------------------------------------------------------------------------
extern "C" void kernel_launch(void* const* d_in, const int* in_sizes, int n_in,
                              void* d_out, int out_size) {
    const float* h    = (const float*)d_in[0];
    const float* Wr   = (const float*)d_in[1];
    const float* U    = (const float*)d_in[2];
    const float* V    = (const float*)d_in[3];
    const float* attr = (const float*)d_in[4];
    const float* Wa   = (const float*)d_in[5];
    float* out = (float*)d_out;

    reset_kernel<<<1, 32>>>();
    router_kernel<<<TTOT / 64, 256>>>(h, Wr, attr, Wa);
    scan_kernel<<<1, 32>>>();
    hu_kernel<<<dim3(TTOT / 128, SDIM, 2), 256>>>(h, U);
    outA_kernel<<<dim3(TTOT / 128, SDIM, 4), 256>>>(V);
    gather_kernel<<<TTOT, 256>>>(out);
}

// round 6
// speedup vs baseline: 2.5366x; 1.0943x over previous
#include <cuda_runtime.h>
#include <math.h>

// Fixed shapes: B*T = 8192 tokens, H = 2048, S = 32, r = 16, ad = 32, topk = 2
#define HDIM 2048
#define SDIM 32
#define RDIM 16
#define ADIM 32
#define TTOT 8192

// ---- static device scratch ----
__device__ int   d_c[2][SDIM];                    // [list][schema] counts
__device__ int   d_tok[2][SDIM * TTOT];           // bucket -> token
__device__ float d_g[2][SDIM * TTOT];             // bucket -> coeff g*alpha
__device__ __align__(16) float d_hU[8][SDIM * TTOT * RDIM];  // [list*4+kz] partials

// ---- cp.async helpers ----
__device__ __forceinline__ void cp16(void* dst_smem, const void* src) {
    unsigned d = (unsigned)__cvta_generic_to_shared(dst_smem);
    asm volatile("cp.async.cg.shared.global [%0], [%1], 16;" :: "r"(d), "l"(src));
}
__device__ __forceinline__ void cp_commit() { asm volatile("cp.async.commit_group;"); }
template <int N> __device__ __forceinline__ void cp_wait() {
    asm volatile("cp.async.wait_group %0;" :: "n"(N));
}

// ---------------------------------------------------------------------------
// Kernel 0: reset bucket counters
// ---------------------------------------------------------------------------
__global__ void reset_kernel() {
    if (threadIdx.x < 2 * SDIM) d_c[threadIdx.x >> 5][threadIdx.x & 31] = 0;
}

// ---------------------------------------------------------------------------
// Kernel 1: router GEMM (64 tok x 32 s, cp.async double buffered) +
// per-thread serial top-2/softmax/gate + scatter into primary/secondary lists.
// ---------------------------------------------------------------------------
__global__ void __launch_bounds__(256) router_kernel(
    const float* __restrict__ h, const float* __restrict__ Wr,
    const float* __restrict__ attr, const float* __restrict__ Wa) {
    __shared__ float4 sh[2][64 * 9];   // 8 data chunks + 1 pad per row
    __shared__ float4 sw[2][32 * 9];
    __shared__ float  ssc[64][33];
    __shared__ float  saw[SDIM];

    int tid = threadIdx.x;
    int t0  = blockIdx.x * 64;

    if (tid < SDIM) {
        float a = 0.f;
#pragma unroll
        for (int j = 0; j < ADIM; j++) a += attr[tid * ADIM + j] * Wa[j];
        saw[tid] = 1.0f / (1.0f + expf(-a));
    }

    int tg = tid & 31, sg = tid >> 5;
    float acc0[4] = {0.f, 0.f, 0.f, 0.f};
    float acc1[4] = {0.f, 0.f, 0.f, 0.f};

    const int NT = HDIM / 32;   // 64 K-tiles

    auto load_tile = [&](int kt, int b) {
        int k0 = kt * 32;
#pragma unroll
        for (int i = tid; i < 512; i += 256) {
            int row = i >> 3, c = i & 7;
            cp16(&sh[b][row * 9 + c], h + (size_t)(t0 + row) * HDIM + k0 + c * 4);
        }
        {
            int row = tid >> 3, c = tid & 7;
            cp16(&sw[b][row * 9 + c], Wr + (size_t)row * HDIM + k0 + c * 4);
        }
        cp_commit();
    };

    load_tile(0, 0);
    for (int kt = 0; kt < NT; kt++) {
        int b = kt & 1;
        if (kt + 1 < NT) { load_tile(kt + 1, b ^ 1); cp_wait<1>(); }
        else             { cp_wait<0>(); }
        __syncthreads();
        const float4* H4 = sh[b];
        const float4* W4 = sw[b];
#pragma unroll
        for (int c = 0; c < 8; c++) {
            float4 a0 = H4[tg * 9 + c];
            float4 a1 = H4[(tg + 32) * 9 + c];
#pragma unroll
            for (int j = 0; j < 4; j++) {
                float4 w = W4[(4 * sg + j) * 9 + c];
                acc0[j] += a0.x * w.x; acc0[j] += a0.y * w.y;
                acc0[j] += a0.z * w.z; acc0[j] += a0.w * w.w;
                acc1[j] += a1.x * w.x; acc1[j] += a1.y * w.y;
                acc1[j] += a1.z * w.z; acc1[j] += a1.w * w.w;
            }
        }
        __syncthreads();
    }

#pragma unroll
    for (int j = 0; j < 4; j++) {
        ssc[tg][4 * sg + j]      = acc0[j];
        ssc[tg + 32][4 * sg + j] = acc1[j];
    }
    __syncthreads();

    if (tid < 64) {   // strictly serial per-thread top-2 + softmax (no collectives)
        int t = t0 + tid;
        float m = ssc[tid][0];
        int   i1 = 0;
#pragma unroll
        for (int s2 = 1; s2 < SDIM; s2++) {
            float v = ssc[tid][s2];
            if (v > m) { m = v; i1 = s2; }
        }
        float m2 = -3.4e38f;
        int   i2 = (i1 == 0) ? 1 : 0;
#pragma unroll
        for (int s2 = 0; s2 < SDIM; s2++) {
            if (s2 == i1) continue;
            float v = ssc[tid][s2];
            if (v > m2) { m2 = v; i2 = s2; }
        }
        float Z = 0.f;
#pragma unroll
        for (int s2 = 0; s2 < SDIM; s2++) Z += expf(ssc[tid][s2] - m);
        float g0 = 1.0f / Z;
        float g1 = expf(m2 - m) / Z;
        float gs = g0 + g1 + 1e-8f;
        g0 /= gs; g1 /= gs;
        float alpha = 0.9f + 0.2f * (g0 * saw[i1] + g1 * saw[i2]);

        int p1 = atomicAdd(&d_c[0][i1], 1);
        int p2 = atomicAdd(&d_c[1][i2], 1);
        if (p1 >= TTOT) p1 = TTOT - 1;   // unreachable; hard guard
        if (p2 >= TTOT) p2 = TTOT - 1;
        d_tok[0][i1 * TTOT + p1] = t;
        d_g  [0][i1 * TTOT + p1] = g0 * alpha;
        d_tok[1][i2 * TTOT + p2] = t;
        d_g  [1][i2 * TTOT + p2] = g1 * alpha;
    }
}

// ---------------------------------------------------------------------------
// Kernel 2: grouped hU = h_rows @ U[s]. z = list*4 + kz (K quarter of 512).
// 128 assignments x 16 r per block; K tiles of 32, cp.async double buffered.
// ---------------------------------------------------------------------------
__global__ void __launch_bounds__(256) hu_kernel(
    const float* __restrict__ h, const float* __restrict__ U) {
    int s = blockIdx.y;
    int z = blockIdx.z;
    int l = z >> 2, kz = z & 3;
    int base = blockIdx.x * 128;
    int n = d_c[l][s] - base;
    if (n <= 0) return;
    if (n > 128) n = 128;

    __shared__ float4 sh[2][128 * 9];
    __shared__ float4 su[2][32 * 4];
    __shared__ int stok[128];

    int tid = threadIdx.x;
    if (tid < 128) {
        int slot = (tid < n) ? tid : 0;
        stok[tid] = d_tok[l][s * TTOT + base + slot];
    }
    __syncthreads();

    int tg = tid & 63, rg = tid >> 6;
    float acc0[4] = {0.f, 0.f, 0.f, 0.f};
    float acc1[4] = {0.f, 0.f, 0.f, 0.f};
    int k0base = kz * (HDIM / 4);
    const int NT = (HDIM / 4) / 32;   // 16 K-tiles

    auto load_tile = [&](int kt, int b) {
        int k0 = k0base + kt * 32;
#pragma unroll
        for (int i = tid; i < 1024; i += 256) {
            int row = i >> 3, c = i & 7;
            cp16(&sh[b][row * 9 + c], h + (size_t)stok[row] * HDIM + k0 + c * 4);
        }
        if (tid < 128) {
            int k = tid >> 2, c = tid & 3;
            cp16(&su[b][k * 4 + c],
                 U + (size_t)s * HDIM * RDIM + (size_t)(k0 + k) * RDIM + c * 4);
        }
        cp_commit();
    };

    load_tile(0, 0);
    for (int kt = 0; kt < NT; kt++) {
        int b = kt & 1;
        if (kt + 1 < NT) { load_tile(kt + 1, b ^ 1); cp_wait<1>(); }
        else             { cp_wait<0>(); }
        __syncthreads();
        const float4* H4 = sh[b];
        const float4* U4 = su[b];
#pragma unroll
        for (int c = 0; c < 8; c++) {
            float4 a0 = H4[tg * 9 + c];
            float4 a1 = H4[(tg + 64) * 9 + c];
            float a0v[4] = {a0.x, a0.y, a0.z, a0.w};
            float a1v[4] = {a1.x, a1.y, a1.z, a1.w};
#pragma unroll
            for (int i = 0; i < 4; i++) {
                float4 bb = U4[(4 * c + i) * 4 + rg];   // warp broadcast
                acc0[0] += a0v[i] * bb.x; acc0[1] += a0v[i] * bb.y;
                acc0[2] += a0v[i] * bb.z; acc0[3] += a0v[i] * bb.w;
                acc1[0] += a1v[i] * bb.x; acc1[1] += a1v[i] * bb.y;
                acc1[2] += a1v[i] * bb.z; acc1[3] += a1v[i] * bb.w;
            }
        }
        __syncthreads();
    }

    float* hu = d_hU[z];
    if (tg < n)
        *(float4*)&hu[(size_t)(s * TTOT + base + tg) * RDIM + 4 * rg] =
            make_float4(acc0[0], acc0[1], acc0[2], acc0[3]);
    if (tg + 64 < n)
        *(float4*)&hu[(size_t)(s * TTOT + base + tg + 64) * RDIM + 4 * rg] =
            make_float4(acc1[0], acc1[1], acc1[2], acc1[3]);
}

// ---------------------------------------------------------------------------
// Kernel 3: (c * hU) @ V[s] for a 512-wide H slice, written DIRECTLY to out.
// pass 0 = primary assignments: plain store (covers every token exactly once).
// pass 1 = secondary: load + add + store. Stream order => deterministic.
// ---------------------------------------------------------------------------
__global__ void __launch_bounds__(256) outP_kernel(
    const float* __restrict__ V, float* __restrict__ out, int pass) {
    int s = blockIdx.y;
    int base = blockIdx.x * 128;
    int hq = blockIdx.z;
    int n = d_c[pass][s] - base;
    if (n <= 0) return;
    if (n > 128) n = 128;

    __shared__ float  shu[128][17];
    __shared__ float4 sv[2][16 * 32];
    __shared__ int stok[128];

    int tid = threadIdx.x;
    if (tid < 128) {
        int slot = (tid < n) ? tid : 0;
        stok[tid] = d_tok[pass][s * TTOT + base + slot];
    }
    for (int idx = tid; idx < 128 * 16; idx += 256) {
        int slot = idx >> 4, r = idx & 15;
        float v = 0.f;
        if (slot < n) {
            size_t a = (size_t)(s * TTOT + base + slot) * RDIM + r;
            int q0 = pass * 4;
            v = d_g[pass][s * TTOT + base + slot] *
                (((d_hU[q0][a] + d_hU[q0 + 1][a]) + d_hU[q0 + 2][a]) + d_hU[q0 + 3][a]);
        }
        shu[slot][r] = v;
    }

    int h0 = hq * 512;
    int hg = tid & 7, tokg = tid >> 3;
    const float* Vs = V + (size_t)s * RDIM * HDIM;

    auto load_tile = [&](int ht, int b) {
#pragma unroll
        for (int i = tid; i < 512; i += 256) {
            int r = i >> 5, c = i & 31;
            cp16(&sv[b][r * 32 + c], Vs + (size_t)r * HDIM + h0 + ht * 128 + c * 4);
        }
        cp_commit();
    };

    load_tile(0, 0);
    for (int ht = 0; ht < 4; ht++) {
        int b = ht & 1;
        if (ht + 1 < 4) { load_tile(ht + 1, b ^ 1); cp_wait<1>(); }
        else            { cp_wait<0>(); }
        __syncthreads();

        float4 acc[4][4];
#pragma unroll
        for (int i = 0; i < 4; i++)
#pragma unroll
            for (int j = 0; j < 4; j++) acc[i][j] = make_float4(0.f, 0.f, 0.f, 0.f);

        const float4* V4 = sv[b];
#pragma unroll
        for (int r = 0; r < 16; r++) {
            float a0 = shu[tokg][r];
            float a1 = shu[tokg + 32][r];
            float a2 = shu[tokg + 64][r];
            float a3 = shu[tokg + 96][r];
#pragma unroll
            for (int jj = 0; jj < 4; jj++) {
                float4 bb = V4[r * 32 + hg + 8 * jj];   // phase-distinct banks
                acc[0][jj].x += a0 * bb.x; acc[0][jj].y += a0 * bb.y;
                acc[0][jj].z += a0 * bb.z; acc[0][jj].w += a0 * bb.w;
                acc[1][jj].x += a1 * bb.x; acc[1][jj].y += a1 * bb.y;
                acc[1][jj].z += a1 * bb.z; acc[1][jj].w += a1 * bb.w;
                acc[2][jj].x += a2 * bb.x; acc[2][jj].y += a2 * bb.y;
                acc[2][jj].z += a2 * bb.z; acc[2][jj].w += a2 * bb.w;
                acc[3][jj].x += a3 * bb.x; acc[3][jj].y += a3 * bb.y;
                acc[3][jj].z += a3 * bb.z; acc[3][jj].w += a3 * bb.w;
            }
        }

#pragma unroll
        for (int i = 0; i < 4; i++) {
            int slot = tokg + 32 * i;
            if (slot < n) {
                float* p = out + (size_t)stok[slot] * HDIM + h0 + ht * 128 + 4 * hg;
                if (pass == 0) {
#pragma unroll
                    for (int jj = 0; jj < 4; jj++)
                        *(float4*)(p + 32 * jj) = acc[i][jj];
                } else {
#pragma unroll
                    for (int jj = 0; jj < 4; jj++) {
                        float4 o = *(float4*)(p + 32 * jj);
                        o.x += acc[i][jj].x; o.y += acc[i][jj].y;
                        o.z += acc[i][jj].z; o.w += acc[i][jj].w;
                        *(float4*)(p + 32 * jj) = o;
                    }
                }
            }
        }
        __syncthreads();
    }
}

// ---------------------------------------------------------------------------
// Launch
// ---------------------------------------------------------------------------
extern "C" void kernel_launch(void* const* d_in, const int* in_sizes, int n_in,
                              void* d_out, int out_size) {
    const float* h    = (const float*)d_in[0];
    const float* Wr   = (const float*)d_in[1];
    const float* U    = (const float*)d_in[2];
    const float* V    = (const float*)d_in[3];
    const float* attr = (const float*)d_in[4];
    const float* Wa   = (const float*)d_in[5];
    float* out = (float*)d_out;

    reset_kernel<<<1, 64>>>();
    router_kernel<<<TTOT / 64, 256>>>(h, Wr, attr, Wa);
    hu_kernel<<<dim3(TTOT / 128, SDIM, 8), 256>>>(h, U);
    outP_kernel<<<dim3(TTOT / 128, SDIM, 4), 256>>>(V, out, 0);
    outP_kernel<<<dim3(TTOT / 128, SDIM, 4), 256>>>(V, out, 1);
}

// round 10
// speedup vs baseline: 2.6577x; 1.0477x over previous
#include <cuda_runtime.h>
#include <math.h>

// Fixed shapes: B*T = 8192 tokens, H = 2048, S = 32, r = 16, ad = 32, topk = 2
#define HDIM 2048
#define SDIM 32
#define RDIM 16
#define ADIM 32
#define TTOT 8192

typedef unsigned long long u64;

// ---- static device scratch ----
__device__ int   d_c[2][SDIM];                    // [list][schema] counts
__device__ int   d_tok[2][SDIM * TTOT];           // bucket -> token
__device__ float d_g[2][SDIM * TTOT];             // bucket -> coeff g*alpha
__device__ __align__(16) float d_hU[8][SDIM * TTOT * RDIM];  // [list*4+kz] partials

// ---- cp.async helpers ----
__device__ __forceinline__ void cp16(void* dst_smem, const void* src) {
    unsigned d = (unsigned)__cvta_generic_to_shared(dst_smem);
    asm volatile("cp.async.cg.shared.global [%0], [%1], 16;" :: "r"(d), "l"(src));
}
__device__ __forceinline__ void cp_commit() { asm volatile("cp.async.commit_group;"); }
template <int N> __device__ __forceinline__ void cp_wait() {
    asm volatile("cp.async.wait_group %0;" :: "n"(N));
}

// ---- packed f32x2 helpers (FFMA2). Packing is across INDEPENDENT accumulator
// lanes only -> results are bitwise identical to the scalar version. ----
__device__ __forceinline__ u64 pack2(float x, float y) {
    u64 r; asm("mov.b64 %0, {%1, %2};" : "=l"(r) : "f"(x), "f"(y)); return r;
}
__device__ __forceinline__ void ffma2(u64& d, u64 a, u64 b) {
    asm("fma.rn.f32x2 %0, %1, %2, %3;" : "=l"(d) : "l"(a), "l"(b), "l"(d));
}
__device__ __forceinline__ float2 unpack2(u64 p) {
    float2 f; asm("mov.b64 {%0, %1}, %2;" : "=f"(f.x), "=f"(f.y) : "l"(p)); return f;
}

// ---------------------------------------------------------------------------
// Kernel 0: reset bucket counters
// ---------------------------------------------------------------------------
__global__ void reset_kernel() {
    if (threadIdx.x < 2 * SDIM) d_c[threadIdx.x >> 5][threadIdx.x & 31] = 0;
}

// ---------------------------------------------------------------------------
// Kernel 1: router GEMM (scalar FMA on purpose: keeps top-2 selection
// bit-stable) + serial per-thread top-2/softmax/gate + bucket scatter.
// ---------------------------------------------------------------------------
__global__ void __launch_bounds__(256) router_kernel(
    const float* __restrict__ h, const float* __restrict__ Wr,
    const float* __restrict__ attr, const float* __restrict__ Wa) {
    __shared__ float4 sh[2][64 * 9];   // 8 data chunks + 1 pad per row
    __shared__ float4 sw[2][32 * 9];
    __shared__ float  ssc[64][33];
    __shared__ float  saw[SDIM];

    int tid = threadIdx.x;
    int t0  = blockIdx.x * 64;

    if (tid < SDIM) {
        float a = 0.f;
#pragma unroll
        for (int j = 0; j < ADIM; j++) a += attr[tid * ADIM + j] * Wa[j];
        saw[tid] = 1.0f / (1.0f + expf(-a));
    }

    int tg = tid & 31, sg = tid >> 5;
    float acc0[4] = {0.f, 0.f, 0.f, 0.f};
    float acc1[4] = {0.f, 0.f, 0.f, 0.f};

    const int NT = HDIM / 32;   // 64 K-tiles

    auto load_tile = [&](int kt, int b) {
        int k0 = kt * 32;
#pragma unroll
        for (int i = tid; i < 512; i += 256) {
            int row = i >> 3, c = i & 7;
            cp16(&sh[b][row * 9 + c], h + (size_t)(t0 + row) * HDIM + k0 + c * 4);
        }
        {
            int row = tid >> 3, c = tid & 7;
            cp16(&sw[b][row * 9 + c], Wr + (size_t)row * HDIM + k0 + c * 4);
        }
        cp_commit();
    };

    load_tile(0, 0);
    for (int kt = 0; kt < NT; kt++) {
        int b = kt & 1;
        if (kt + 1 < NT) { load_tile(kt + 1, b ^ 1); cp_wait<1>(); }
        else             { cp_wait<0>(); }
        __syncthreads();
        const float4* H4 = sh[b];
        const float4* W4 = sw[b];
#pragma unroll
        for (int c = 0; c < 8; c++) {
            float4 a0 = H4[tg * 9 + c];
            float4 a1 = H4[(tg + 32) * 9 + c];
#pragma unroll
            for (int j = 0; j < 4; j++) {
                float4 w = W4[(4 * sg + j) * 9 + c];
                acc0[j] += a0.x * w.x; acc0[j] += a0.y * w.y;
                acc0[j] += a0.z * w.z; acc0[j] += a0.w * w.w;
                acc1[j] += a1.x * w.x; acc1[j] += a1.y * w.y;
                acc1[j] += a1.z * w.z; acc1[j] += a1.w * w.w;
            }
        }
        __syncthreads();
    }

#pragma unroll
    for (int j = 0; j < 4; j++) {
        ssc[tg][4 * sg + j]      = acc0[j];
        ssc[tg + 32][4 * sg + j] = acc1[j];
    }
    __syncthreads();

    if (tid < 64) {   // strictly serial per-thread top-2 + softmax (no collectives)
        int t = t0 + tid;
        float m = ssc[tid][0];
        int   i1 = 0;
#pragma unroll
        for (int s2 = 1; s2 < SDIM; s2++) {
            float v = ssc[tid][s2];
            if (v > m) { m = v; i1 = s2; }
        }
        float m2 = -3.4e38f;
        int   i2 = (i1 == 0) ? 1 : 0;
#pragma unroll
        for (int s2 = 0; s2 < SDIM; s2++) {
            if (s2 == i1) continue;
            float v = ssc[tid][s2];
            if (v > m2) { m2 = v; i2 = s2; }
        }
        float Z = 0.f;
#pragma unroll
        for (int s2 = 0; s2 < SDIM; s2++) Z += expf(ssc[tid][s2] - m);
        float g0 = 1.0f / Z;
        float g1 = expf(m2 - m) / Z;
        float gs = g0 + g1 + 1e-8f;
        g0 /= gs; g1 /= gs;
        float alpha = 0.9f + 0.2f * (g0 * saw[i1] + g1 * saw[i2]);

        int p1 = atomicAdd(&d_c[0][i1], 1);
        int p2 = atomicAdd(&d_c[1][i2], 1);
        if (p1 >= TTOT) p1 = TTOT - 1;   // unreachable; hard guard
        if (p2 >= TTOT) p2 = TTOT - 1;
        d_tok[0][i1 * TTOT + p1] = t;
        d_g  [0][i1 * TTOT + p1] = g0 * alpha;
        d_tok[1][i2 * TTOT + p2] = t;
        d_g  [1][i2 * TTOT + p2] = g1 * alpha;
    }
}

// ---------------------------------------------------------------------------
// Kernel 2: grouped hU = h_rows @ U[s]. z = list*4 + kz (K quarter of 512).
// Inner product uses fma.rn.f32x2 packed across r-pairs (bitwise identical).
// ---------------------------------------------------------------------------
__global__ void __launch_bounds__(256) hu_kernel(
    const float* __restrict__ h, const float* __restrict__ U) {
    int s = blockIdx.y;
    int z = blockIdx.z;
    int l = z >> 2, kz = z & 3;
    int base = blockIdx.x * 128;
    int n = d_c[l][s] - base;
    if (n <= 0) return;
    if (n > 128) n = 128;

    __shared__ float4 sh[2][128 * 9];
    __shared__ __align__(16) float4 su[2][32 * 4];
    __shared__ int stok[128];

    int tid = threadIdx.x;
    if (tid < 128) {
        int slot = (tid < n) ? tid : 0;
        stok[tid] = d_tok[l][s * TTOT + base + slot];
    }
    __syncthreads();

    int tg = tid & 63, rg = tid >> 6;
    u64 acc0p[2] = {0ull, 0ull};   // r pair {4rg,4rg+1}, {4rg+2,4rg+3} for token tg
    u64 acc1p[2] = {0ull, 0ull};   // same for token tg+64
    int k0base = kz * (HDIM / 4);
    const int NT = (HDIM / 4) / 32;   // 16 K-tiles

    auto load_tile = [&](int kt, int b) {
        int k0 = k0base + kt * 32;
#pragma unroll
        for (int i = tid; i < 1024; i += 256) {
            int row = i >> 3, c = i & 7;
            cp16(&sh[b][row * 9 + c], h + (size_t)stok[row] * HDIM + k0 + c * 4);
        }
        if (tid < 128) {
            int k = tid >> 2, c = tid & 3;
            cp16(&su[b][k * 4 + c],
                 U + (size_t)s * HDIM * RDIM + (size_t)(k0 + k) * RDIM + c * 4);
        }
        cp_commit();
    };

    load_tile(0, 0);
    for (int kt = 0; kt < NT; kt++) {
        int b = kt & 1;
        if (kt + 1 < NT) { load_tile(kt + 1, b ^ 1); cp_wait<1>(); }
        else             { cp_wait<0>(); }
        __syncthreads();
        const float4* H4 = sh[b];
        const u64*    U8 = (const u64*)su[b];
#pragma unroll
        for (int c = 0; c < 8; c++) {
            float4 a0 = H4[tg * 9 + c];
            float4 a1 = H4[(tg + 64) * 9 + c];
            float a0v[4] = {a0.x, a0.y, a0.z, a0.w};
            float a1v[4] = {a1.x, a1.y, a1.z, a1.w};
#pragma unroll
            for (int i = 0; i < 4; i++) {
                int ui = ((4 * c + i) * 4 + rg) * 2;   // warp-broadcast pairs
                u64 b0 = U8[ui], b1 = U8[ui + 1];
                u64 pa0 = pack2(a0v[i], a0v[i]);
                u64 pa1 = pack2(a1v[i], a1v[i]);
                ffma2(acc0p[0], pa0, b0); ffma2(acc0p[1], pa0, b1);
                ffma2(acc1p[0], pa1, b0); ffma2(acc1p[1], pa1, b1);
            }
        }
        __syncthreads();
    }

    float* hu = d_hU[z];
    float2 r00 = unpack2(acc0p[0]), r01 = unpack2(acc0p[1]);
    float2 r10 = unpack2(acc1p[0]), r11 = unpack2(acc1p[1]);
    if (tg < n)
        *(float4*)&hu[(size_t)(s * TTOT + base + tg) * RDIM + 4 * rg] =
            make_float4(r00.x, r00.y, r01.x, r01.y);
    if (tg + 64 < n)
        *(float4*)&hu[(size_t)(s * TTOT + base + tg + 64) * RDIM + 4 * rg] =
            make_float4(r10.x, r10.y, r11.x, r11.y);
}

// ---------------------------------------------------------------------------
// Kernel 3: (c * hU) @ V[s] for a 512-wide H slice, written DIRECTLY to out.
// pass 0 = primary: plain store (every token exactly once). pass 1 =
// secondary: load+add+store. FFMA2 packed across h-lane pairs (bitwise ident.)
// ---------------------------------------------------------------------------
__global__ void __launch_bounds__(256) outP_kernel(
    const float* __restrict__ V, float* __restrict__ out, int pass) {
    int s = blockIdx.y;
    int base = blockIdx.x * 128;
    int hq = blockIdx.z;
    int n = d_c[pass][s] - base;
    if (n <= 0) return;
    if (n > 128) n = 128;

    __shared__ float  shu[128][17];
    __shared__ __align__(16) float4 sv[2][16 * 32];
    __shared__ int stok[128];

    int tid = threadIdx.x;
    if (tid < 128) {
        int slot = (tid < n) ? tid : 0;
        stok[tid] = d_tok[pass][s * TTOT + base + slot];
    }
    for (int idx = tid; idx < 128 * 16; idx += 256) {
        int slot = idx >> 4, r = idx & 15;
        float v = 0.f;
        if (slot < n) {
            size_t a = (size_t)(s * TTOT + base + slot) * RDIM + r;
            int q0 = pass * 4;
            v = d_g[pass][s * TTOT + base + slot] *
                (((d_hU[q0][a] + d_hU[q0 + 1][a]) + d_hU[q0 + 2][a]) + d_hU[q0 + 3][a]);
        }
        shu[slot][r] = v;
    }

    int h0 = hq * 512;
    int hg = tid & 7, tokg = tid >> 3;
    const float* Vs = V + (size_t)s * RDIM * HDIM;

    auto load_tile = [&](int ht, int b) {
#pragma unroll
        for (int i = tid; i < 512; i += 256) {
            int r = i >> 5, c = i & 31;
            cp16(&sv[b][r * 32 + c], Vs + (size_t)r * HDIM + h0 + ht * 128 + c * 4);
        }
        cp_commit();
    };

    load_tile(0, 0);
    for (int ht = 0; ht < 4; ht++) {
        int b = ht & 1;
        if (ht + 1 < 4) { load_tile(ht + 1, b ^ 1); cp_wait<1>(); }
        else            { cp_wait<0>(); }
        __syncthreads();

        u64 accp[4][4][2];   // [token i][jj][h-pair]
#pragma unroll
        for (int i = 0; i < 4; i++)
#pragma unroll
            for (int j = 0; j < 4; j++) { accp[i][j][0] = 0ull; accp[i][j][1] = 0ull; }

        const u64* V8 = (const u64*)sv[b];
#pragma unroll
        for (int r = 0; r < 16; r++) {
            u64 pa0 = pack2(shu[tokg][r],      shu[tokg][r]);
            u64 pa1 = pack2(shu[tokg + 32][r], shu[tokg + 32][r]);
            u64 pa2 = pack2(shu[tokg + 64][r], shu[tokg + 64][r]);
            u64 pa3 = pack2(shu[tokg + 96][r], shu[tokg + 96][r]);
#pragma unroll
            for (int jj = 0; jj < 4; jj++) {
                int vi = (r * 32 + hg + 8 * jj) * 2;   // phase-distinct banks
                u64 b0 = V8[vi], b1 = V8[vi + 1];
                ffma2(accp[0][jj][0], pa0, b0); ffma2(accp[0][jj][1], pa0, b1);
                ffma2(accp[1][jj][0], pa1, b0); ffma2(accp[1][jj][1], pa1, b1);
                ffma2(accp[2][jj][0], pa2, b0); ffma2(accp[2][jj][1], pa2, b1);
                ffma2(accp[3][jj][0], pa3, b0); ffma2(accp[3][jj][1], pa3, b1);
            }
        }

#pragma unroll
        for (int i = 0; i < 4; i++) {
            int slot = tokg + 32 * i;
            if (slot < n) {
                float* p = out + (size_t)stok[slot] * HDIM + h0 + ht * 128 + 4 * hg;
                if (pass == 0) {
#pragma unroll
                    for (int jj = 0; jj < 4; jj++) {
                        float2 lo = unpack2(accp[i][jj][0]);
                        float2 hi = unpack2(accp[i][jj][1]);
                        *(float4*)(p + 32 * jj) = make_float4(lo.x, lo.y, hi.x, hi.y);
                    }
                } else {
#pragma unroll
                    for (int jj = 0; jj < 4; jj++) {
                        float2 lo = unpack2(accp[i][jj][0]);
                        float2 hi = unpack2(accp[i][jj][1]);
                        float4 o = *(float4*)(p + 32 * jj);
                        o.x += lo.x; o.y += lo.y; o.z += hi.x; o.w += hi.y;
                        *(float4*)(p + 32 * jj) = o;
                    }
                }
            }
        }
        __syncthreads();
    }
}

// ---------------------------------------------------------------------------
// Launch
// ---------------------------------------------------------------------------
extern "C" void kernel_launch(void* const* d_in, const int* in_sizes, int n_in,
                              void* d_out, int out_size) {
    const float* h    = (const float*)d_in[0];
    const float* Wr   = (const float*)d_in[1];
    const float* U    = (const float*)d_in[2];
    const float* V    = (const float*)d_in[3];
    const float* attr = (const float*)d_in[4];
    const float* Wa   = (const float*)d_in[5];
    float* out = (float*)d_out;

    reset_kernel<<<1, 64>>>();
    router_kernel<<<TTOT / 64, 256>>>(h, Wr, attr, Wa);
    hu_kernel<<<dim3(TTOT / 128, SDIM, 8), 256>>>(h, U);
    outP_kernel<<<dim3(TTOT / 128, SDIM, 4), 256>>>(V, out, 0);
    outP_kernel<<<dim3(TTOT / 128, SDIM, 4), 256>>>(V, out, 1);
}